// round 13
// baseline (speedup 1.0000x reference)
#include <cuda_runtime.h>
#include <cuda_fp16.h>
#include <cstdint>

#define N_NODES 100000
#define E_EDGES 3200000
#define NTILES  6250        // 100000 / 16 exactly
#define LN_EPS  1e-5f
#define TPB     256
#define WPB     8

// ---------------- scratch ----------------------------------------------------
__device__ __align__(16) float g_agg_in [N_NODES * 16];
__device__ __align__(16) float g_agg_out[N_NODES * 16];
__device__ __align__(16) uint2 g_nh     [N_NODES * 4];   // nodes as fp16 (half2 pairs)

// ---------------- prep: zero agg + convert nodes to fp16 (replaces memsets) --
__global__ void __launch_bounds__(256)
prep_kernel(const float* __restrict__ nodes) {
    int i = blockIdx.x * 256 + threadIdx.x;
    if (i >= N_NODES * 4) return;
    float4 v = ((const float4*)nodes)[i];
    __half2 h0 = __floats2half2_rn(v.x, v.y);
    __half2 h1 = __floats2half2_rn(v.z, v.w);
    uint2 packed;
    packed.x = *reinterpret_cast<uint32_t*>(&h0);
    packed.y = *reinterpret_cast<uint32_t*>(&h1);
    g_nh[i] = packed;
    ((float4*)g_agg_in )[i] = make_float4(0.f, 0.f, 0.f, 0.f);
    ((float4*)g_agg_out)[i] = make_float4(0.f, 0.f, 0.f, 0.f);
}

// ---------------- edge scatter (fp16 gather, fp32 RED) -----------------------
__device__ __forceinline__ void red_add_v4(float* p, float a, float b, float c, float d) {
    asm volatile("red.global.add.v4.f32 [%0], {%1,%2,%3,%4};"
                 :: "l"(p), "f"(a), "f"(b), "f"(c), "f"(d) : "memory");
}

__global__ void __launch_bounds__(256)
scatter_kernel(const int2*  __restrict__ edges,
               const float* __restrict__ ew) {
    int tid = blockIdx.x * 256 + threadIdx.x;
    int e = tid >> 2;
    if (e >= E_EDGES) return;
    int q = tid & 3;                       // quarter: 4 floats = 1 uint2 of halfs
    int2  sd = edges[e];
    float w  = ew[e];
    uint2 hs = g_nh[sd.x * 4 + q];
    uint2 hd = g_nh[sd.y * 4 + q];
    float2 s0 = __half22float2(*reinterpret_cast<__half2*>(&hs.x));
    float2 s1 = __half22float2(*reinterpret_cast<__half2*>(&hs.y));
    float2 d0 = __half22float2(*reinterpret_cast<__half2*>(&hd.x));
    float2 d1 = __half22float2(*reinterpret_cast<__half2*>(&hd.y));
    red_add_v4(&g_agg_in [sd.y * 16 + q * 4], s0.x * w, s0.y * w, s1.x * w, s1.y * w);
    red_add_v4(&g_agg_out[sd.x * 16 + q * 4], d0.x * w, d0.y * w, d1.x * w, d1.y * w);
}

// ============ warp-MMA MLP (fp16 2-term split, fragment-major B) =============
#define OFF_L1 0
#define OFF_L2 3072
#define OFF_L3 11264
#define OFF_L4 19456
#define OFF_PB 20480
#define SMEM_U32 (OFF_PB + 1200)
#define SMEM_BYTES (SMEM_U32 * 4)

__device__ __forceinline__ void mma16816f(float d[4], const uint32_t a[4],
                                          uint32_t b0, uint32_t b1) {
    asm volatile("mma.sync.aligned.m16n8k16.row.col.f32.f16.f16.f32 "
                 "{%0,%1,%2,%3}, {%4,%5,%6,%7}, {%8,%9}, {%0,%1,%2,%3};"
                 : "+f"(d[0]), "+f"(d[1]), "+f"(d[2]), "+f"(d[3])
                 : "r"(a[0]), "r"(a[1]), "r"(a[2]), "r"(a[3]), "r"(b0), "r"(b1));
}
__device__ __forceinline__ void mma16816f_z(float d[4], const uint32_t a[4],
                                            uint32_t b0, uint32_t b1) {
    asm volatile("mma.sync.aligned.m16n8k16.row.col.f32.f16.f16.f32 "
                 "{%0,%1,%2,%3}, {%4,%5,%6,%7}, {%8,%9}, {%10,%10,%10,%10};"
                 : "=f"(d[0]), "=f"(d[1]), "=f"(d[2]), "=f"(d[3])
                 : "r"(a[0]), "r"(a[1]), "r"(a[2]), "r"(a[3]), "r"(b0), "r"(b1),
                   "f"(0.0f));
}

__device__ __forceinline__ void ldsm2(uint32_t& r0, uint32_t& r1, uint32_t addr) {
    asm volatile("ldmatrix.sync.aligned.m8n8.x2.shared.b16 {%0,%1}, [%2];"
                 : "=r"(r0), "=r"(r1) : "r"(addr));
}

__device__ __forceinline__ uint32_t smem_u32(const void* p) {
    uint32_t a;
    asm("{ .reg .u64 t; cvta.to.shared.u64 t, %1; cvt.u32.u64 %0, t; }" : "=r"(a) : "l"(p));
    return a;
}

// fp16 split: hi + residual
__device__ __forceinline__ uint32_t pack_hi(float a, float b, float& ra, float& rb) {
    __half2 h2 = __floats2half2_rn(a, b);
    ra = a - __half2float(__low2half(h2));
    rb = b - __half2float(__high2half(h2));
    return *reinterpret_cast<uint32_t*>(&h2);
}
__device__ __forceinline__ uint32_t pack_f16(float a, float b) {
    __half2 h2 = __floats2half2_rn(a, b);
    return *reinterpret_cast<uint32_t*>(&h2);
}

__device__ __forceinline__ float ptanh(float x) {
    float y;
    asm("tanh.approx.f32 %0, %1;" : "=f"(y) : "f"(x));
    return y;
}
__device__ __forceinline__ float ftanh(float x) {
    float t = fminf(fmaxf(2.0f * x, -60.0f), 60.0f);
    float e = __expf(t);
    return __fdividef(e - 1.0f, e + 1.0f);
}

// stage W[K][N] -> fragment-major blocks
__device__ void stage_w(const float* __restrict__ W, uint32_t* __restrict__ dst,
                        int K, int N, int KT, int tid, int tpb) {
    const int half = K >> 1;
    for (int idx = tid; idx < N * half; idx += tpb) {
        int n = idx / half, kk = idx - n * half;
        int k = 2 * kk;
        int kt = k >> 4, hf = (k >> 3) & 1, kc = (k & 7) >> 1;
        int nt = n >> 3, row = n & 7;
        dst[((nt * KT + kt) * 2 + hf) * 32 + row * 4 + kc] =
            pack_f16(W[k * N + n], W[(k + 1) * N + n]);
    }
}

// D[nt] = (Ahi + Alo) x W ; all ldsm addresses = fbase + immediate
template <int KT, int NTt>
__device__ __forceinline__ void layer_mma(const uint32_t Ahi[][4], const uint32_t Alo[][4],
                                          uint32_t fbase, float D[][4]) {
#pragma unroll
    for (int nt = 0; nt < NTt; nt++) {
        uint32_t b0, b1;
        ldsm2(b0, b1, fbase + (uint32_t)(nt * KT) * 256u);
        mma16816f_z(D[nt], Ahi[0], b0, b1);
        mma16816f(D[nt], Alo[0], b0, b1);
#pragma unroll
        for (int kt = 1; kt < KT; kt++) {
            ldsm2(b0, b1, fbase + (uint32_t)(nt * KT + kt) * 256u);
            mma16816f(D[nt], Ahi[kt], b0, b1);
            mma16816f(D[nt], Alo[kt], b0, b1);
        }
    }
}

// bias + LN(128) + tanh on D, emit next-layer A fragments (hi/lo fp16)
__device__ __forceinline__ void epi128(float D[][4], const float* __restrict__ Pb, int base,
                                       int tig, uint32_t Ahi[][4], uint32_t Alo[][4]) {
    const float* bias = Pb + base;
    const float* gain = Pb + base + 128;
    const float* beta = Pb + base + 256;
    float s0 = 0.f, q0 = 0.f, s1 = 0.f, q1 = 0.f;
#pragma unroll
    for (int nt = 0; nt < 16; nt++) {
        float2 bb = *(const float2*)&bias[nt * 8 + tig * 2];
        D[nt][0] += bb.x; D[nt][1] += bb.y;
        D[nt][2] += bb.x; D[nt][3] += bb.y;
        s0 += D[nt][0] + D[nt][1];
        q0 = fmaf(D[nt][0], D[nt][0], fmaf(D[nt][1], D[nt][1], q0));
        s1 += D[nt][2] + D[nt][3];
        q1 = fmaf(D[nt][2], D[nt][2], fmaf(D[nt][3], D[nt][3], q1));
    }
    s0 += __shfl_xor_sync(0xffffffffu, s0, 1); q0 += __shfl_xor_sync(0xffffffffu, q0, 1);
    s0 += __shfl_xor_sync(0xffffffffu, s0, 2); q0 += __shfl_xor_sync(0xffffffffu, q0, 2);
    s1 += __shfl_xor_sync(0xffffffffu, s1, 1); q1 += __shfl_xor_sync(0xffffffffu, q1, 1);
    s1 += __shfl_xor_sync(0xffffffffu, s1, 2); q1 += __shfl_xor_sync(0xffffffffu, q1, 2);
    float m0 = s0 * (1.0f / 128.0f);
    float v0 = fmaxf(q0 * (1.0f / 128.0f) - m0 * m0, 0.0f);
    float rs0 = rsqrtf(v0 + LN_EPS);
    float m1 = s1 * (1.0f / 128.0f);
    float v1 = fmaxf(q1 * (1.0f / 128.0f) - m1 * m1, 0.0f);
    float rs1 = rsqrtf(v1 + LN_EPS);
#pragma unroll
    for (int kt = 0; kt < 8; kt++) {
#pragma unroll
        for (int h = 0; h < 2; h++) {
            int nt = 2 * kt + h;
            float2 gg = *(const float2*)&gain[nt * 8 + tig * 2];
            float2 be = *(const float2*)&beta[nt * 8 + tig * 2];
            float y0 = ptanh(fmaf((D[nt][0] - m0) * rs0, gg.x, be.x));
            float y1 = ptanh(fmaf((D[nt][1] - m0) * rs0, gg.y, be.y));
            float y2 = ptanh(fmaf((D[nt][2] - m1) * rs1, gg.x, be.x));
            float y3 = ptanh(fmaf((D[nt][3] - m1) * rs1, gg.y, be.y));
            float ra, rb;
            Ahi[kt][0 + 2 * h] = pack_hi(y0, y1, ra, rb);
            Alo[kt][0 + 2 * h] = pack_f16(ra, rb);
            Ahi[kt][1 + 2 * h] = pack_hi(y2, y3, ra, rb);
            Alo[kt][1 + 2 * h] = pack_f16(ra, rb);
        }
    }
}

__global__ void __launch_bounds__(TPB, 1)
mlp_kernel(const float* __restrict__ nodes,
           const float* __restrict__ W1, const float* __restrict__ b1,
           const float* __restrict__ g1, const float* __restrict__ be1,
           const float* __restrict__ W2, const float* __restrict__ b2,
           const float* __restrict__ g2, const float* __restrict__ be2,
           const float* __restrict__ W3, const float* __restrict__ b3,
           const float* __restrict__ g3, const float* __restrict__ be3,
           const float* __restrict__ W4, const float* __restrict__ b4,
           const float* __restrict__ g4, const float* __restrict__ be4,
           float* __restrict__ out) {
    extern __shared__ uint32_t smw[];
    float* Pb = (float*)(smw + OFF_PB);
    const int tid = threadIdx.x;

    // ---- stage weights (fp16, fragment-major) ----
    stage_w(W1, smw + OFF_L1,  48, 128, 3, tid, TPB);
    stage_w(W2, smw + OFF_L2, 128, 128, 8, tid, TPB);
    stage_w(W3, smw + OFF_L3, 128, 128, 8, tid, TPB);
    stage_w(W4, smw + OFF_L4, 128,  16, 8, tid, TPB);
    for (int i = tid; i < 128; i += TPB) {
        Pb[0 + i]   = b1[i]; Pb[128 + i] = g1[i]; Pb[256 + i]  = be1[i];
        Pb[384 + i] = b2[i]; Pb[512 + i] = g2[i]; Pb[640 + i]  = be2[i];
        Pb[768 + i] = b3[i]; Pb[896 + i] = g3[i]; Pb[1024 + i] = be3[i];
    }
    for (int i = tid; i < 16; i += TPB) {
        Pb[1152 + i] = b4[i]; Pb[1168 + i] = g4[i]; Pb[1184 + i] = be4[i];
    }
    __syncthreads();

    const int warp = tid >> 5, lane = tid & 31;
    const int grp = lane >> 2, tig = lane & 3;
    const int lane16 = lane & 15;
    const uint32_t fconst = (uint32_t)(lane16 >> 3) * 128u + (uint32_t)(lane16 & 7) * 16u;
    const uint32_t smbase = smem_u32(smw);
    const uint32_t fb1 = smbase + OFF_L1 * 4u + fconst;
    const uint32_t fb2 = smbase + OFF_L2 * 4u + fconst;
    const uint32_t fb3 = smbase + OFF_L3 * 4u + fconst;
    const uint32_t fb4 = smbase + OFF_L4 * 4u + fconst;

    uint32_t Ahi[8][4], Alo[8][4];
    float D[16][4];

    for (int t = blockIdx.x * WPB + warp; t < NTILES; t += gridDim.x * WPB) {
        const int r0 = t * 16 + grp, r1 = r0 + 8;

        // ---- layer-1 A fragments from [agg_in | agg_out | nodes] ----
#pragma unroll
        for (int kt = 0; kt < 3; kt++) {
            const float* S = (kt == 0) ? g_agg_in : (kt == 1) ? g_agg_out : nodes;
            float2 x00 = *(const float2*)&S[r0 * 16 + tig * 2];
            float2 x01 = *(const float2*)&S[r0 * 16 + 8 + tig * 2];
            float2 x10 = *(const float2*)&S[r1 * 16 + tig * 2];
            float2 x11 = *(const float2*)&S[r1 * 16 + 8 + tig * 2];
            float ra, rb;
            Ahi[kt][0] = pack_hi(x00.x, x00.y, ra, rb); Alo[kt][0] = pack_f16(ra, rb);
            Ahi[kt][1] = pack_hi(x10.x, x10.y, ra, rb); Alo[kt][1] = pack_f16(ra, rb);
            Ahi[kt][2] = pack_hi(x01.x, x01.y, ra, rb); Alo[kt][2] = pack_f16(ra, rb);
            Ahi[kt][3] = pack_hi(x11.x, x11.y, ra, rb); Alo[kt][3] = pack_f16(ra, rb);
        }

        layer_mma<3, 16>(Ahi, Alo, fb1, D);
        epi128(D, Pb, 0, tig, Ahi, Alo);
        layer_mma<8, 16>(Ahi, Alo, fb2, D);
        epi128(D, Pb, 384, tig, Ahi, Alo);
        layer_mma<8, 16>(Ahi, Alo, fb3, D);
        epi128(D, Pb, 768, tig, Ahi, Alo);
        layer_mma<8, 2>(Ahi, Alo, fb4, D);

        // ---- layer-4 epilogue: LN(16)+tanh (accurate), write out ----
        {
            float2 bb0 = *(const float2*)&Pb[1152 + tig * 2];
            float2 bb1 = *(const float2*)&Pb[1152 + 8 + tig * 2];
            float v00 = D[0][0] + bb0.x, v01 = D[0][1] + bb0.y;
            float v02 = D[1][0] + bb1.x, v03 = D[1][1] + bb1.y;
            float v10 = D[0][2] + bb0.x, v11 = D[0][3] + bb0.y;
            float v12 = D[1][2] + bb1.x, v13 = D[1][3] + bb1.y;
            float s0 = (v00 + v01) + (v02 + v03);
            float q0 = fmaf(v00, v00, fmaf(v01, v01, fmaf(v02, v02, v03 * v03)));
            float s1 = (v10 + v11) + (v12 + v13);
            float q1 = fmaf(v10, v10, fmaf(v11, v11, fmaf(v12, v12, v13 * v13)));
            s0 += __shfl_xor_sync(0xffffffffu, s0, 1); q0 += __shfl_xor_sync(0xffffffffu, q0, 1);
            s0 += __shfl_xor_sync(0xffffffffu, s0, 2); q0 += __shfl_xor_sync(0xffffffffu, q0, 2);
            s1 += __shfl_xor_sync(0xffffffffu, s1, 1); q1 += __shfl_xor_sync(0xffffffffu, q1, 1);
            s1 += __shfl_xor_sync(0xffffffffu, s1, 2); q1 += __shfl_xor_sync(0xffffffffu, q1, 2);
            float m0 = s0 * (1.0f / 16.0f);
            float w0 = fmaxf(q0 * (1.0f / 16.0f) - m0 * m0, 0.0f);
            float rs0 = rsqrtf(w0 + LN_EPS);
            float m1 = s1 * (1.0f / 16.0f);
            float w1 = fmaxf(q1 * (1.0f / 16.0f) - m1 * m1, 0.0f);
            float rs1 = rsqrtf(w1 + LN_EPS);
            float2 gg0 = *(const float2*)&Pb[1168 + tig * 2];
            float2 gg1 = *(const float2*)&Pb[1168 + 8 + tig * 2];
            float2 be0 = *(const float2*)&Pb[1184 + tig * 2];
            float2 be1v = *(const float2*)&Pb[1184 + 8 + tig * 2];
            float2 o;
            o.x = ftanh(fmaf((v00 - m0) * rs0, gg0.x, be0.x));
            o.y = ftanh(fmaf((v01 - m0) * rs0, gg0.y, be0.y));
            *(float2*)&out[r0 * 16 + tig * 2] = o;
            o.x = ftanh(fmaf((v02 - m0) * rs0, gg1.x, be1v.x));
            o.y = ftanh(fmaf((v03 - m0) * rs0, gg1.y, be1v.y));
            *(float2*)&out[r0 * 16 + 8 + tig * 2] = o;
            o.x = ftanh(fmaf((v10 - m1) * rs1, gg0.x, be0.x));
            o.y = ftanh(fmaf((v11 - m1) * rs1, gg0.y, be0.y));
            *(float2*)&out[r1 * 16 + tig * 2] = o;
            o.x = ftanh(fmaf((v12 - m1) * rs1, gg1.x, be1v.x));
            o.y = ftanh(fmaf((v13 - m1) * rs1, gg1.y, be1v.y));
            *(float2*)&out[r1 * 16 + 8 + tig * 2] = o;
        }
    }
}

// ---------------- launch -----------------------------------------------------
extern "C" void kernel_launch(void* const* d_in, const int* in_sizes, int n_in,
                              void* d_out, int out_size) {
    const float* nodes = (const float*)d_in[0];
    const int2*  edges = (const int2*) d_in[1];
    const float* ew    = (const float*)d_in[2];
    const float* W1 = (const float*)d_in[3];
    const float* b1 = (const float*)d_in[4];
    const float* g1 = (const float*)d_in[5];
    const float* be1= (const float*)d_in[6];
    const float* W2 = (const float*)d_in[7];
    const float* b2 = (const float*)d_in[8];
    const float* g2 = (const float*)d_in[9];
    const float* be2= (const float*)d_in[10];
    const float* W3 = (const float*)d_in[11];
    const float* b3 = (const float*)d_in[12];
    const float* g3 = (const float*)d_in[13];
    const float* be3= (const float*)d_in[14];
    const float* W4 = (const float*)d_in[15];
    const float* b4 = (const float*)d_in[16];
    const float* g4 = (const float*)d_in[17];
    const float* be4= (const float*)d_in[18];
    float* out = (float*)d_out;

    // prep: zero agg + fp16 node copy (single node, replaces both memsets)
    prep_kernel<<<(N_NODES * 4 + 255) / 256, 256>>>(nodes);
    // scatter: fp16 gather, fp32 RED
    scatter_kernel<<<(E_EDGES * 4 + 255) / 256, 256>>>(edges, ew);

    int smCount = 148;
    cudaDeviceGetAttribute(&smCount, cudaDevAttrMultiProcessorCount, 0);
    cudaFuncSetAttribute(mlp_kernel, cudaFuncAttributeMaxDynamicSharedMemorySize, SMEM_BYTES);
    mlp_kernel<<<smCount, TPB, SMEM_BYTES>>>(nodes,
                                             W1, b1, g1, be1,
                                             W2, b2, g2, be2,
                                             W3, b3, g3, be3,
                                             W4, b4, g4, be4,
                                             out);
}

// round 14
// speedup vs baseline: 1.6074x; 1.6074x over previous
#include <cuda_runtime.h>
#include <cuda_fp16.h>
#include <cstdint>

#define N_NODES 100000
#define E_EDGES 3200000
#define NTILES  6250        // 100000 / 16 exactly
#define LN_EPS  1e-5f
#define TPB     256
#define WPB     8

// ---------------- scratch ----------------------------------------------------
__device__ __align__(16) float g_agg_in [N_NODES * 16];
__device__ __align__(16) float g_agg_out[N_NODES * 16];

// ---------------- edge scatter (2 edges / thread, fp32) ----------------------
__device__ __forceinline__ void red_add_v4(float* p, float a, float b, float c, float d) {
    asm volatile("red.global.add.v4.f32 [%0], {%1,%2,%3,%4};"
                 :: "l"(p), "f"(a), "f"(b), "f"(c), "f"(d) : "memory");
}

__global__ void __launch_bounds__(256)
scatter_kernel(const float* __restrict__ nodes,
               const int4*  __restrict__ edges2,    // (s0,d0,s1,d1) edge pairs
               const float2* __restrict__ ew2) {
    int tid = blockIdx.x * 256 + threadIdx.x;
    int pe = tid >> 2;                     // edge-pair index
    if (pe >= E_EDGES / 2) return;
    int c4 = (tid & 3) * 4;
    int4   sd = edges2[pe];
    float2 w  = ew2[pe];
    float4 ns0 = *(const float4*)&nodes[sd.x * 16 + c4];
    float4 nd0 = *(const float4*)&nodes[sd.y * 16 + c4];
    float4 ns1 = *(const float4*)&nodes[sd.z * 16 + c4];
    float4 nd1 = *(const float4*)&nodes[sd.w * 16 + c4];
    red_add_v4(&g_agg_in [sd.y * 16 + c4], ns0.x * w.x, ns0.y * w.x, ns0.z * w.x, ns0.w * w.x);
    red_add_v4(&g_agg_out[sd.x * 16 + c4], nd0.x * w.x, nd0.y * w.x, nd0.z * w.x, nd0.w * w.x);
    red_add_v4(&g_agg_in [sd.w * 16 + c4], ns1.x * w.y, ns1.y * w.y, ns1.z * w.y, ns1.w * w.y);
    red_add_v4(&g_agg_out[sd.z * 16 + c4], nd1.x * w.y, nd1.y * w.y, nd1.z * w.y, nd1.w * w.y);
}

// ============ warp-MMA MLP (fp16 2-term split, fragment-major B) =============
#define OFF_L1 0
#define OFF_L2 3072
#define OFF_L3 11264
#define OFF_L4 19456
#define OFF_PB 20480
#define SMEM_U32 (OFF_PB + 1200)
#define SMEM_BYTES (SMEM_U32 * 4)

__device__ __forceinline__ void mma16816f(float d[4], const uint32_t a[4],
                                          uint32_t b0, uint32_t b1) {
    asm volatile("mma.sync.aligned.m16n8k16.row.col.f32.f16.f16.f32 "
                 "{%0,%1,%2,%3}, {%4,%5,%6,%7}, {%8,%9}, {%0,%1,%2,%3};"
                 : "+f"(d[0]), "+f"(d[1]), "+f"(d[2]), "+f"(d[3])
                 : "r"(a[0]), "r"(a[1]), "r"(a[2]), "r"(a[3]), "r"(b0), "r"(b1));
}
__device__ __forceinline__ void mma16816f_z(float d[4], const uint32_t a[4],
                                            uint32_t b0, uint32_t b1) {
    asm volatile("mma.sync.aligned.m16n8k16.row.col.f32.f16.f16.f32 "
                 "{%0,%1,%2,%3}, {%4,%5,%6,%7}, {%8,%9}, {%10,%10,%10,%10};"
                 : "=f"(d[0]), "=f"(d[1]), "=f"(d[2]), "=f"(d[3])
                 : "r"(a[0]), "r"(a[1]), "r"(a[2]), "r"(a[3]), "r"(b0), "r"(b1),
                   "f"(0.0f));
}

__device__ __forceinline__ void ldsm2(uint32_t& r0, uint32_t& r1, uint32_t addr) {
    asm volatile("ldmatrix.sync.aligned.m8n8.x2.shared.b16 {%0,%1}, [%2];"
                 : "=r"(r0), "=r"(r1) : "r"(addr));
}

__device__ __forceinline__ uint32_t smem_u32(const void* p) {
    uint32_t a;
    asm("{ .reg .u64 t; cvta.to.shared.u64 t, %1; cvt.u32.u64 %0, t; }" : "=r"(a) : "l"(p));
    return a;
}

// fp16 split: hi + residual
__device__ __forceinline__ uint32_t pack_hi(float a, float b, float& ra, float& rb) {
    __half2 h2 = __floats2half2_rn(a, b);
    ra = a - __half2float(__low2half(h2));
    rb = b - __half2float(__high2half(h2));
    return *reinterpret_cast<uint32_t*>(&h2);
}
__device__ __forceinline__ uint32_t pack_f16(float a, float b) {
    __half2 h2 = __floats2half2_rn(a, b);
    return *reinterpret_cast<uint32_t*>(&h2);
}

__device__ __forceinline__ float ptanh(float x) {
    float y;
    asm("tanh.approx.f32 %0, %1;" : "=f"(y) : "f"(x));
    return y;
}
__device__ __forceinline__ float ftanh(float x) {
    float t = fminf(fmaxf(2.0f * x, -60.0f), 60.0f);
    float e = __expf(t);
    return __fdividef(e - 1.0f, e + 1.0f);
}

// stage W[K][N] -> fragment-major blocks
__device__ void stage_w(const float* __restrict__ W, uint32_t* __restrict__ dst,
                        int K, int N, int KT, int tid, int tpb) {
    const int half = K >> 1;
    for (int idx = tid; idx < N * half; idx += tpb) {
        int n = idx / half, kk = idx - n * half;
        int k = 2 * kk;
        int kt = k >> 4, hf = (k >> 3) & 1, kc = (k & 7) >> 1;
        int nt = n >> 3, row = n & 7;
        dst[((nt * KT + kt) * 2 + hf) * 32 + row * 4 + kc] =
            pack_f16(W[k * N + n], W[(k + 1) * N + n]);
    }
}

// D[nt] = (Ahi + Alo) x W ; all ldsm addresses = fbase + immediate
template <int KT, int NTt>
__device__ __forceinline__ void layer_mma(const uint32_t Ahi[][4], const uint32_t Alo[][4],
                                          uint32_t fbase, float D[][4]) {
#pragma unroll
    for (int nt = 0; nt < NTt; nt++) {
        uint32_t b0, b1;
        ldsm2(b0, b1, fbase + (uint32_t)(nt * KT) * 256u);
        mma16816f_z(D[nt], Ahi[0], b0, b1);
        mma16816f(D[nt], Alo[0], b0, b1);
#pragma unroll
        for (int kt = 1; kt < KT; kt++) {
            ldsm2(b0, b1, fbase + (uint32_t)(nt * KT + kt) * 256u);
            mma16816f(D[nt], Ahi[kt], b0, b1);
            mma16816f(D[nt], Alo[kt], b0, b1);
        }
    }
}

// bias + LN(128) + tanh on D, emit next-layer A fragments (hi/lo fp16)
__device__ __forceinline__ void epi128(float D[][4], const float* __restrict__ Pb, int base,
                                       int tig, uint32_t Ahi[][4], uint32_t Alo[][4]) {
    const float* bias = Pb + base;
    const float* gain = Pb + base + 128;
    const float* beta = Pb + base + 256;
    float s0 = 0.f, q0 = 0.f, s1 = 0.f, q1 = 0.f;
#pragma unroll
    for (int nt = 0; nt < 16; nt++) {
        float2 bb = *(const float2*)&bias[nt * 8 + tig * 2];
        D[nt][0] += bb.x; D[nt][1] += bb.y;
        D[nt][2] += bb.x; D[nt][3] += bb.y;
        s0 += D[nt][0] + D[nt][1];
        q0 = fmaf(D[nt][0], D[nt][0], fmaf(D[nt][1], D[nt][1], q0));
        s1 += D[nt][2] + D[nt][3];
        q1 = fmaf(D[nt][2], D[nt][2], fmaf(D[nt][3], D[nt][3], q1));
    }
    s0 += __shfl_xor_sync(0xffffffffu, s0, 1); q0 += __shfl_xor_sync(0xffffffffu, q0, 1);
    s0 += __shfl_xor_sync(0xffffffffu, s0, 2); q0 += __shfl_xor_sync(0xffffffffu, q0, 2);
    s1 += __shfl_xor_sync(0xffffffffu, s1, 1); q1 += __shfl_xor_sync(0xffffffffu, q1, 1);
    s1 += __shfl_xor_sync(0xffffffffu, s1, 2); q1 += __shfl_xor_sync(0xffffffffu, q1, 2);
    float m0 = s0 * (1.0f / 128.0f);
    float v0 = fmaxf(q0 * (1.0f / 128.0f) - m0 * m0, 0.0f);
    float rs0 = rsqrtf(v0 + LN_EPS);
    float m1 = s1 * (1.0f / 128.0f);
    float v1 = fmaxf(q1 * (1.0f / 128.0f) - m1 * m1, 0.0f);
    float rs1 = rsqrtf(v1 + LN_EPS);
#pragma unroll
    for (int kt = 0; kt < 8; kt++) {
#pragma unroll
        for (int h = 0; h < 2; h++) {
            int nt = 2 * kt + h;
            float2 gg = *(const float2*)&gain[nt * 8 + tig * 2];
            float2 be = *(const float2*)&beta[nt * 8 + tig * 2];
            float y0 = ptanh(fmaf((D[nt][0] - m0) * rs0, gg.x, be.x));
            float y1 = ptanh(fmaf((D[nt][1] - m0) * rs0, gg.y, be.y));
            float y2 = ptanh(fmaf((D[nt][2] - m1) * rs1, gg.x, be.x));
            float y3 = ptanh(fmaf((D[nt][3] - m1) * rs1, gg.y, be.y));
            float ra, rb;
            Ahi[kt][0 + 2 * h] = pack_hi(y0, y1, ra, rb);
            Alo[kt][0 + 2 * h] = pack_f16(ra, rb);
            Ahi[kt][1 + 2 * h] = pack_hi(y2, y3, ra, rb);
            Alo[kt][1 + 2 * h] = pack_f16(ra, rb);
        }
    }
}

__global__ void __launch_bounds__(TPB, 1)
mlp_kernel(const float* __restrict__ nodes,
           const float* __restrict__ W1, const float* __restrict__ b1,
           const float* __restrict__ g1, const float* __restrict__ be1,
           const float* __restrict__ W2, const float* __restrict__ b2,
           const float* __restrict__ g2, const float* __restrict__ be2,
           const float* __restrict__ W3, const float* __restrict__ b3,
           const float* __restrict__ g3, const float* __restrict__ be3,
           const float* __restrict__ W4, const float* __restrict__ b4,
           const float* __restrict__ g4, const float* __restrict__ be4,
           float* __restrict__ out) {
    extern __shared__ uint32_t smw[];
    float* Pb = (float*)(smw + OFF_PB);
    const int tid = threadIdx.x;

    // ---- stage weights (fp16, fragment-major) ----
    stage_w(W1, smw + OFF_L1,  48, 128, 3, tid, TPB);
    stage_w(W2, smw + OFF_L2, 128, 128, 8, tid, TPB);
    stage_w(W3, smw + OFF_L3, 128, 128, 8, tid, TPB);
    stage_w(W4, smw + OFF_L4, 128,  16, 8, tid, TPB);
    for (int i = tid; i < 128; i += TPB) {
        Pb[0 + i]   = b1[i]; Pb[128 + i] = g1[i]; Pb[256 + i]  = be1[i];
        Pb[384 + i] = b2[i]; Pb[512 + i] = g2[i]; Pb[640 + i]  = be2[i];
        Pb[768 + i] = b3[i]; Pb[896 + i] = g3[i]; Pb[1024 + i] = be3[i];
    }
    for (int i = tid; i < 16; i += TPB) {
        Pb[1152 + i] = b4[i]; Pb[1168 + i] = g4[i]; Pb[1184 + i] = be4[i];
    }
    __syncthreads();

    const int warp = tid >> 5, lane = tid & 31;
    const int grp = lane >> 2, tig = lane & 3;
    const int lane16 = lane & 15;
    const uint32_t fconst = (uint32_t)(lane16 >> 3) * 128u + (uint32_t)(lane16 & 7) * 16u;
    const uint32_t smbase = smem_u32(smw);
    const uint32_t fb1 = smbase + OFF_L1 * 4u + fconst;
    const uint32_t fb2 = smbase + OFF_L2 * 4u + fconst;
    const uint32_t fb3 = smbase + OFF_L3 * 4u + fconst;
    const uint32_t fb4 = smbase + OFF_L4 * 4u + fconst;

    uint32_t Ahi[8][4], Alo[8][4];
    float D[16][4];

    for (int t = blockIdx.x * WPB + warp; t < NTILES; t += gridDim.x * WPB) {
        const int r0 = t * 16 + grp, r1 = r0 + 8;

        // ---- layer-1 A fragments from [agg_in | agg_out | nodes] ----
#pragma unroll
        for (int kt = 0; kt < 3; kt++) {
            const float* S = (kt == 0) ? g_agg_in : (kt == 1) ? g_agg_out : nodes;
            float2 x00 = *(const float2*)&S[r0 * 16 + tig * 2];
            float2 x01 = *(const float2*)&S[r0 * 16 + 8 + tig * 2];
            float2 x10 = *(const float2*)&S[r1 * 16 + tig * 2];
            float2 x11 = *(const float2*)&S[r1 * 16 + 8 + tig * 2];
            float ra, rb;
            Ahi[kt][0] = pack_hi(x00.x, x00.y, ra, rb); Alo[kt][0] = pack_f16(ra, rb);
            Ahi[kt][1] = pack_hi(x10.x, x10.y, ra, rb); Alo[kt][1] = pack_f16(ra, rb);
            Ahi[kt][2] = pack_hi(x01.x, x01.y, ra, rb); Alo[kt][2] = pack_f16(ra, rb);
            Ahi[kt][3] = pack_hi(x11.x, x11.y, ra, rb); Alo[kt][3] = pack_f16(ra, rb);
        }

        layer_mma<3, 16>(Ahi, Alo, fb1, D);
        epi128(D, Pb, 0, tig, Ahi, Alo);
        layer_mma<8, 16>(Ahi, Alo, fb2, D);
        epi128(D, Pb, 384, tig, Ahi, Alo);
        layer_mma<8, 16>(Ahi, Alo, fb3, D);
        epi128(D, Pb, 768, tig, Ahi, Alo);
        layer_mma<8, 2>(Ahi, Alo, fb4, D);

        // ---- layer-4 epilogue: LN(16)+tanh (accurate), write out ----
        {
            float2 bb0 = *(const float2*)&Pb[1152 + tig * 2];
            float2 bb1 = *(const float2*)&Pb[1152 + 8 + tig * 2];
            float v00 = D[0][0] + bb0.x, v01 = D[0][1] + bb0.y;
            float v02 = D[1][0] + bb1.x, v03 = D[1][1] + bb1.y;
            float v10 = D[0][2] + bb0.x, v11 = D[0][3] + bb0.y;
            float v12 = D[1][2] + bb1.x, v13 = D[1][3] + bb1.y;
            float s0 = (v00 + v01) + (v02 + v03);
            float q0 = fmaf(v00, v00, fmaf(v01, v01, fmaf(v02, v02, v03 * v03)));
            float s1 = (v10 + v11) + (v12 + v13);
            float q1 = fmaf(v10, v10, fmaf(v11, v11, fmaf(v12, v12, v13 * v13)));
            s0 += __shfl_xor_sync(0xffffffffu, s0, 1); q0 += __shfl_xor_sync(0xffffffffu, q0, 1);
            s0 += __shfl_xor_sync(0xffffffffu, s0, 2); q0 += __shfl_xor_sync(0xffffffffu, q0, 2);
            s1 += __shfl_xor_sync(0xffffffffu, s1, 1); q1 += __shfl_xor_sync(0xffffffffu, q1, 1);
            s1 += __shfl_xor_sync(0xffffffffu, s1, 2); q1 += __shfl_xor_sync(0xffffffffu, q1, 2);
            float m0 = s0 * (1.0f / 16.0f);
            float w0 = fmaxf(q0 * (1.0f / 16.0f) - m0 * m0, 0.0f);
            float rs0 = rsqrtf(w0 + LN_EPS);
            float m1 = s1 * (1.0f / 16.0f);
            float w1 = fmaxf(q1 * (1.0f / 16.0f) - m1 * m1, 0.0f);
            float rs1 = rsqrtf(w1 + LN_EPS);
            float2 gg0 = *(const float2*)&Pb[1168 + tig * 2];
            float2 gg1 = *(const float2*)&Pb[1168 + 8 + tig * 2];
            float2 be0 = *(const float2*)&Pb[1184 + tig * 2];
            float2 be1v = *(const float2*)&Pb[1184 + 8 + tig * 2];
            float2 o;
            o.x = ftanh(fmaf((v00 - m0) * rs0, gg0.x, be0.x));
            o.y = ftanh(fmaf((v01 - m0) * rs0, gg0.y, be0.y));
            *(float2*)&out[r0 * 16 + tig * 2] = o;
            o.x = ftanh(fmaf((v02 - m0) * rs0, gg1.x, be1v.x));
            o.y = ftanh(fmaf((v03 - m0) * rs0, gg1.y, be1v.y));
            *(float2*)&out[r0 * 16 + 8 + tig * 2] = o;
            o.x = ftanh(fmaf((v10 - m1) * rs1, gg0.x, be0.x));
            o.y = ftanh(fmaf((v11 - m1) * rs1, gg0.y, be0.y));
            *(float2*)&out[r1 * 16 + tig * 2] = o;
            o.x = ftanh(fmaf((v12 - m1) * rs1, gg1.x, be1v.x));
            o.y = ftanh(fmaf((v13 - m1) * rs1, gg1.y, be1v.y));
            *(float2*)&out[r1 * 16 + 8 + tig * 2] = o;
        }
    }
}

// ---------------- launch -----------------------------------------------------
extern "C" void kernel_launch(void* const* d_in, const int* in_sizes, int n_in,
                              void* d_out, int out_size) {
    const float* nodes = (const float*)d_in[0];
    const int4*  edges2= (const int4*) d_in[1];
    const float2* ew2  = (const float2*)d_in[2];
    const float* W1 = (const float*)d_in[3];
    const float* b1 = (const float*)d_in[4];
    const float* g1 = (const float*)d_in[5];
    const float* be1= (const float*)d_in[6];
    const float* W2 = (const float*)d_in[7];
    const float* b2 = (const float*)d_in[8];
    const float* g2 = (const float*)d_in[9];
    const float* be2= (const float*)d_in[10];
    const float* W3 = (const float*)d_in[11];
    const float* b3 = (const float*)d_in[12];
    const float* g3 = (const float*)d_in[13];
    const float* be3= (const float*)d_in[14];
    const float* W4 = (const float*)d_in[15];
    const float* b4 = (const float*)d_in[16];
    const float* g4 = (const float*)d_in[17];
    const float* be4= (const float*)d_in[18];
    float* out = (float*)d_out;

    // zero agg buffers via memset nodes (graph-capturable, no kernel launch)
    void* p_in = nullptr; void* p_out = nullptr;
    cudaGetSymbolAddress(&p_in,  g_agg_in);
    cudaGetSymbolAddress(&p_out, g_agg_out);
    cudaMemsetAsync(p_in,  0, N_NODES * 16 * sizeof(float));
    cudaMemsetAsync(p_out, 0, N_NODES * 16 * sizeof(float));

    // scatter: 2 edges per thread
    scatter_kernel<<<(E_EDGES / 2 * 4 + 255) / 256, 256>>>(nodes, edges2, ew2);

    int smCount = 148;
    cudaDeviceGetAttribute(&smCount, cudaDevAttrMultiProcessorCount, 0);
    cudaFuncSetAttribute(mlp_kernel, cudaFuncAttributeMaxDynamicSharedMemorySize, SMEM_BYTES);
    mlp_kernel<<<smCount, TPB, SMEM_BYTES>>>(nodes,
                                             W1, b1, g1, be1,
                                             W2, b2, g2, be2,
                                             W3, b3, g3, be3,
                                             W4, b4, g4, be4,
                                             out);
}

// round 15
// speedup vs baseline: 1.6247x; 1.0108x over previous
#include <cuda_runtime.h>
#include <cuda_fp16.h>
#include <cstdint>

#define N_NODES 100000
#define E_EDGES 3200000
#define NTILES  6250        // 100000 / 16 exactly
#define LN_EPS  1e-5f
#define TPB     256
#define WPB     8

// ---------------- scratch ----------------------------------------------------
// starts zeroed (BSS); mlp_kernel re-zeroes consumed rows each run, so the
// zero invariant holds across graph replays without memset nodes.
__device__ __align__(16) float g_agg_in [N_NODES * 16];
__device__ __align__(16) float g_agg_out[N_NODES * 16];

// ---------------- edge scatter (4 edges / thread, fp32) ----------------------
__device__ __forceinline__ void red_add_v4(float* p, float a, float b, float c, float d) {
    asm volatile("red.global.add.v4.f32 [%0], {%1,%2,%3,%4};"
                 :: "l"(p), "f"(a), "f"(b), "f"(c), "f"(d) : "memory");
}

__device__ __forceinline__ void scat1(const float* __restrict__ nodes,
                                      int s, int d, float w, int c4) {
    float4 ns = *(const float4*)&nodes[s * 16 + c4];
    float4 nd = *(const float4*)&nodes[d * 16 + c4];
    red_add_v4(&g_agg_in [d * 16 + c4], ns.x * w, ns.y * w, ns.z * w, ns.w * w);
    red_add_v4(&g_agg_out[s * 16 + c4], nd.x * w, nd.y * w, nd.z * w, nd.w * w);
}

__global__ void __launch_bounds__(256)
scatter_kernel(const float* __restrict__ nodes,
               const int4*  __restrict__ edges4,    // edge pairs: (s,d,s,d)
               const float4* __restrict__ ew4) {
    int tid = blockIdx.x * 256 + threadIdx.x;
    int q = tid >> 2;                      // edge-quad index
    if (q >= E_EDGES / 4) return;
    int c4 = (tid & 3) * 4;
    int4   e01 = edges4[2 * q];
    int4   e23 = edges4[2 * q + 1];
    float4 w   = ew4[q];
    scat1(nodes, e01.x, e01.y, w.x, c4);
    scat1(nodes, e01.z, e01.w, w.y, c4);
    scat1(nodes, e23.x, e23.y, w.z, c4);
    scat1(nodes, e23.z, e23.w, w.w, c4);
}

// ============ warp-MMA MLP (fp16 2-term split, fragment-major B) =============
#define OFF_L1 0
#define OFF_L2 3072
#define OFF_L3 11264
#define OFF_L4 19456
#define OFF_PB 20480
#define SMEM_U32 (OFF_PB + 1200)
#define SMEM_BYTES (SMEM_U32 * 4)

__device__ __forceinline__ void mma16816f(float d[4], const uint32_t a[4],
                                          uint32_t b0, uint32_t b1) {
    asm volatile("mma.sync.aligned.m16n8k16.row.col.f32.f16.f16.f32 "
                 "{%0,%1,%2,%3}, {%4,%5,%6,%7}, {%8,%9}, {%0,%1,%2,%3};"
                 : "+f"(d[0]), "+f"(d[1]), "+f"(d[2]), "+f"(d[3])
                 : "r"(a[0]), "r"(a[1]), "r"(a[2]), "r"(a[3]), "r"(b0), "r"(b1));
}
__device__ __forceinline__ void mma16816f_z(float d[4], const uint32_t a[4],
                                            uint32_t b0, uint32_t b1) {
    asm volatile("mma.sync.aligned.m16n8k16.row.col.f32.f16.f16.f32 "
                 "{%0,%1,%2,%3}, {%4,%5,%6,%7}, {%8,%9}, {%10,%10,%10,%10};"
                 : "=f"(d[0]), "=f"(d[1]), "=f"(d[2]), "=f"(d[3])
                 : "r"(a[0]), "r"(a[1]), "r"(a[2]), "r"(a[3]), "r"(b0), "r"(b1),
                   "f"(0.0f));
}

__device__ __forceinline__ void ldsm2(uint32_t& r0, uint32_t& r1, uint32_t addr) {
    asm volatile("ldmatrix.sync.aligned.m8n8.x2.shared.b16 {%0,%1}, [%2];"
                 : "=r"(r0), "=r"(r1) : "r"(addr));
}

__device__ __forceinline__ uint32_t smem_u32(const void* p) {
    uint32_t a;
    asm("{ .reg .u64 t; cvta.to.shared.u64 t, %1; cvt.u32.u64 %0, t; }" : "=r"(a) : "l"(p));
    return a;
}

// fp16 split: hi + residual
__device__ __forceinline__ uint32_t pack_hi(float a, float b, float& ra, float& rb) {
    __half2 h2 = __floats2half2_rn(a, b);
    ra = a - __half2float(__low2half(h2));
    rb = b - __half2float(__high2half(h2));
    return *reinterpret_cast<uint32_t*>(&h2);
}
__device__ __forceinline__ uint32_t pack_f16(float a, float b) {
    __half2 h2 = __floats2half2_rn(a, b);
    return *reinterpret_cast<uint32_t*>(&h2);
}

__device__ __forceinline__ float ptanh(float x) {
    float y;
    asm("tanh.approx.f32 %0, %1;" : "=f"(y) : "f"(x));
    return y;
}
__device__ __forceinline__ float ftanh(float x) {
    float t = fminf(fmaxf(2.0f * x, -60.0f), 60.0f);
    float e = __expf(t);
    return __fdividef(e - 1.0f, e + 1.0f);
}

// stage W[K][N] -> fragment-major blocks
__device__ void stage_w(const float* __restrict__ W, uint32_t* __restrict__ dst,
                        int K, int N, int KT, int tid, int tpb) {
    const int half = K >> 1;
    for (int idx = tid; idx < N * half; idx += tpb) {
        int n = idx / half, kk = idx - n * half;
        int k = 2 * kk;
        int kt = k >> 4, hf = (k >> 3) & 1, kc = (k & 7) >> 1;
        int nt = n >> 3, row = n & 7;
        dst[((nt * KT + kt) * 2 + hf) * 32 + row * 4 + kc] =
            pack_f16(W[k * N + n], W[(k + 1) * N + n]);
    }
}

// D[nt] = (Ahi + Alo) x W ; all ldsm addresses = fbase + immediate
template <int KT, int NTt>
__device__ __forceinline__ void layer_mma(const uint32_t Ahi[][4], const uint32_t Alo[][4],
                                          uint32_t fbase, float D[][4]) {
#pragma unroll
    for (int nt = 0; nt < NTt; nt++) {
        uint32_t b0, b1;
        ldsm2(b0, b1, fbase + (uint32_t)(nt * KT) * 256u);
        mma16816f_z(D[nt], Ahi[0], b0, b1);
        mma16816f(D[nt], Alo[0], b0, b1);
#pragma unroll
        for (int kt = 1; kt < KT; kt++) {
            ldsm2(b0, b1, fbase + (uint32_t)(nt * KT + kt) * 256u);
            mma16816f(D[nt], Ahi[kt], b0, b1);
            mma16816f(D[nt], Alo[kt], b0, b1);
        }
    }
}

// bias + LN(128) + tanh on D, emit next-layer A fragments (hi/lo fp16)
__device__ __forceinline__ void epi128(float D[][4], const float* __restrict__ Pb, int base,
                                       int tig, uint32_t Ahi[][4], uint32_t Alo[][4]) {
    const float* bias = Pb + base;
    const float* gain = Pb + base + 128;
    const float* beta = Pb + base + 256;
    float s0 = 0.f, q0 = 0.f, s1 = 0.f, q1 = 0.f;
#pragma unroll
    for (int nt = 0; nt < 16; nt++) {
        float2 bb = *(const float2*)&bias[nt * 8 + tig * 2];
        D[nt][0] += bb.x; D[nt][1] += bb.y;
        D[nt][2] += bb.x; D[nt][3] += bb.y;
        s0 += D[nt][0] + D[nt][1];
        q0 = fmaf(D[nt][0], D[nt][0], fmaf(D[nt][1], D[nt][1], q0));
        s1 += D[nt][2] + D[nt][3];
        q1 = fmaf(D[nt][2], D[nt][2], fmaf(D[nt][3], D[nt][3], q1));
    }
    s0 += __shfl_xor_sync(0xffffffffu, s0, 1); q0 += __shfl_xor_sync(0xffffffffu, q0, 1);
    s0 += __shfl_xor_sync(0xffffffffu, s0, 2); q0 += __shfl_xor_sync(0xffffffffu, q0, 2);
    s1 += __shfl_xor_sync(0xffffffffu, s1, 1); q1 += __shfl_xor_sync(0xffffffffu, q1, 1);
    s1 += __shfl_xor_sync(0xffffffffu, s1, 2); q1 += __shfl_xor_sync(0xffffffffu, q1, 2);
    float m0 = s0 * (1.0f / 128.0f);
    float v0 = fmaxf(q0 * (1.0f / 128.0f) - m0 * m0, 0.0f);
    float rs0 = rsqrtf(v0 + LN_EPS);
    float m1 = s1 * (1.0f / 128.0f);
    float v1 = fmaxf(q1 * (1.0f / 128.0f) - m1 * m1, 0.0f);
    float rs1 = rsqrtf(v1 + LN_EPS);
#pragma unroll
    for (int kt = 0; kt < 8; kt++) {
#pragma unroll
        for (int h = 0; h < 2; h++) {
            int nt = 2 * kt + h;
            float2 gg = *(const float2*)&gain[nt * 8 + tig * 2];
            float2 be = *(const float2*)&beta[nt * 8 + tig * 2];
            float y0 = ptanh(fmaf((D[nt][0] - m0) * rs0, gg.x, be.x));
            float y1 = ptanh(fmaf((D[nt][1] - m0) * rs0, gg.y, be.y));
            float y2 = ptanh(fmaf((D[nt][2] - m1) * rs1, gg.x, be.x));
            float y3 = ptanh(fmaf((D[nt][3] - m1) * rs1, gg.y, be.y));
            float ra, rb;
            Ahi[kt][0 + 2 * h] = pack_hi(y0, y1, ra, rb);
            Alo[kt][0 + 2 * h] = pack_f16(ra, rb);
            Ahi[kt][1 + 2 * h] = pack_hi(y2, y3, ra, rb);
            Alo[kt][1 + 2 * h] = pack_f16(ra, rb);
        }
    }
}

__global__ void __launch_bounds__(TPB, 1)
mlp_kernel(const float* __restrict__ nodes,
           const float* __restrict__ W1, const float* __restrict__ b1,
           const float* __restrict__ g1, const float* __restrict__ be1,
           const float* __restrict__ W2, const float* __restrict__ b2,
           const float* __restrict__ g2, const float* __restrict__ be2,
           const float* __restrict__ W3, const float* __restrict__ b3,
           const float* __restrict__ g3, const float* __restrict__ be3,
           const float* __restrict__ W4, const float* __restrict__ b4,
           const float* __restrict__ g4, const float* __restrict__ be4,
           float* __restrict__ out) {
    extern __shared__ uint32_t smw[];
    float* Pb = (float*)(smw + OFF_PB);
    const int tid = threadIdx.x;

    // ---- stage weights (fp16, fragment-major) ----
    stage_w(W1, smw + OFF_L1,  48, 128, 3, tid, TPB);
    stage_w(W2, smw + OFF_L2, 128, 128, 8, tid, TPB);
    stage_w(W3, smw + OFF_L3, 128, 128, 8, tid, TPB);
    stage_w(W4, smw + OFF_L4, 128,  16, 8, tid, TPB);
    for (int i = tid; i < 128; i += TPB) {
        Pb[0 + i]   = b1[i]; Pb[128 + i] = g1[i]; Pb[256 + i]  = be1[i];
        Pb[384 + i] = b2[i]; Pb[512 + i] = g2[i]; Pb[640 + i]  = be2[i];
        Pb[768 + i] = b3[i]; Pb[896 + i] = g3[i]; Pb[1024 + i] = be3[i];
    }
    for (int i = tid; i < 16; i += TPB) {
        Pb[1152 + i] = b4[i]; Pb[1168 + i] = g4[i]; Pb[1184 + i] = be4[i];
    }
    __syncthreads();

    const int warp = tid >> 5, lane = tid & 31;
    const int grp = lane >> 2, tig = lane & 3;
    const int lane16 = lane & 15;
    const uint32_t fconst = (uint32_t)(lane16 >> 3) * 128u + (uint32_t)(lane16 & 7) * 16u;
    const uint32_t smbase = smem_u32(smw);
    const uint32_t fb1 = smbase + OFF_L1 * 4u + fconst;
    const uint32_t fb2 = smbase + OFF_L2 * 4u + fconst;
    const uint32_t fb3 = smbase + OFF_L3 * 4u + fconst;
    const uint32_t fb4 = smbase + OFF_L4 * 4u + fconst;

    uint32_t Ahi[8][4], Alo[8][4];
    float D[16][4];

    for (int t = blockIdx.x * WPB + warp; t < NTILES; t += gridDim.x * WPB) {
        const int r0 = t * 16 + grp, r1 = r0 + 8;

        // ---- layer-1 A fragments from [agg_in | agg_out | nodes] ----
#pragma unroll
        for (int kt = 0; kt < 3; kt++) {
            const float* S = (kt == 0) ? g_agg_in : (kt == 1) ? g_agg_out : nodes;
            float2 x00 = *(const float2*)&S[r0 * 16 + tig * 2];
            float2 x01 = *(const float2*)&S[r0 * 16 + 8 + tig * 2];
            float2 x10 = *(const float2*)&S[r1 * 16 + tig * 2];
            float2 x11 = *(const float2*)&S[r1 * 16 + 8 + tig * 2];
            float ra, rb;
            Ahi[kt][0] = pack_hi(x00.x, x00.y, ra, rb); Alo[kt][0] = pack_f16(ra, rb);
            Ahi[kt][1] = pack_hi(x10.x, x10.y, ra, rb); Alo[kt][1] = pack_f16(ra, rb);
            Ahi[kt][2] = pack_hi(x01.x, x01.y, ra, rb); Alo[kt][2] = pack_f16(ra, rb);
            Ahi[kt][3] = pack_hi(x11.x, x11.y, ra, rb); Alo[kt][3] = pack_f16(ra, rb);
        }

        layer_mma<3, 16>(Ahi, Alo, fb1, D);
        epi128(D, Pb, 0, tig, Ahi, Alo);
        layer_mma<8, 16>(Ahi, Alo, fb2, D);
        epi128(D, Pb, 384, tig, Ahi, Alo);
        layer_mma<8, 16>(Ahi, Alo, fb3, D);
        epi128(D, Pb, 768, tig, Ahi, Alo);
        layer_mma<8, 2>(Ahi, Alo, fb4, D);

        // ---- layer-4 epilogue: LN(16)+tanh (accurate), write out ----
        {
            float2 bb0 = *(const float2*)&Pb[1152 + tig * 2];
            float2 bb1 = *(const float2*)&Pb[1152 + 8 + tig * 2];
            float v00 = D[0][0] + bb0.x, v01 = D[0][1] + bb0.y;
            float v02 = D[1][0] + bb1.x, v03 = D[1][1] + bb1.y;
            float v10 = D[0][2] + bb0.x, v11 = D[0][3] + bb0.y;
            float v12 = D[1][2] + bb1.x, v13 = D[1][3] + bb1.y;
            float s0 = (v00 + v01) + (v02 + v03);
            float q0 = fmaf(v00, v00, fmaf(v01, v01, fmaf(v02, v02, v03 * v03)));
            float s1 = (v10 + v11) + (v12 + v13);
            float q1 = fmaf(v10, v10, fmaf(v11, v11, fmaf(v12, v12, v13 * v13)));
            s0 += __shfl_xor_sync(0xffffffffu, s0, 1); q0 += __shfl_xor_sync(0xffffffffu, q0, 1);
            s0 += __shfl_xor_sync(0xffffffffu, s0, 2); q0 += __shfl_xor_sync(0xffffffffu, q0, 2);
            s1 += __shfl_xor_sync(0xffffffffu, s1, 1); q1 += __shfl_xor_sync(0xffffffffu, q1, 1);
            s1 += __shfl_xor_sync(0xffffffffu, s1, 2); q1 += __shfl_xor_sync(0xffffffffu, q1, 2);
            float m0 = s0 * (1.0f / 16.0f);
            float w0 = fmaxf(q0 * (1.0f / 16.0f) - m0 * m0, 0.0f);
            float rs0 = rsqrtf(w0 + LN_EPS);
            float m1 = s1 * (1.0f / 16.0f);
            float w1 = fmaxf(q1 * (1.0f / 16.0f) - m1 * m1, 0.0f);
            float rs1 = rsqrtf(w1 + LN_EPS);
            float2 gg0 = *(const float2*)&Pb[1168 + tig * 2];
            float2 gg1 = *(const float2*)&Pb[1168 + 8 + tig * 2];
            float2 be0 = *(const float2*)&Pb[1184 + tig * 2];
            float2 be1v = *(const float2*)&Pb[1184 + 8 + tig * 2];
            float2 o;
            o.x = ftanh(fmaf((v00 - m0) * rs0, gg0.x, be0.x));
            o.y = ftanh(fmaf((v01 - m0) * rs0, gg0.y, be0.y));
            *(float2*)&out[r0 * 16 + tig * 2] = o;
            o.x = ftanh(fmaf((v02 - m0) * rs0, gg1.x, be1v.x));
            o.y = ftanh(fmaf((v03 - m0) * rs0, gg1.y, be1v.y));
            *(float2*)&out[r0 * 16 + 8 + tig * 2] = o;
            o.x = ftanh(fmaf((v10 - m1) * rs1, gg0.x, be0.x));
            o.y = ftanh(fmaf((v11 - m1) * rs1, gg0.y, be0.y));
            *(float2*)&out[r1 * 16 + tig * 2] = o;
            o.x = ftanh(fmaf((v12 - m1) * rs1, gg1.x, be1v.x));
            o.y = ftanh(fmaf((v13 - m1) * rs1, gg1.y, be1v.y));
            *(float2*)&out[r1 * 16 + 8 + tig * 2] = o;
        }

        // ---- re-zero this tile's agg rows for the next graph replay ----
        // (tile is warp-exclusive; loads above retired long ago)
        {
            const float4 z = make_float4(0.f, 0.f, 0.f, 0.f);
            *(float4*)&g_agg_in [r0 * 16 + tig * 4] = z;
            *(float4*)&g_agg_in [r1 * 16 + tig * 4] = z;
            *(float4*)&g_agg_out[r0 * 16 + tig * 4] = z;
            *(float4*)&g_agg_out[r1 * 16 + tig * 4] = z;
        }
    }
}

// ---------------- launch -----------------------------------------------------
extern "C" void kernel_launch(void* const* d_in, const int* in_sizes, int n_in,
                              void* d_out, int out_size) {
    const float* nodes  = (const float*)d_in[0];
    const int4*  edges4 = (const int4*) d_in[1];
    const float4* ew4   = (const float4*)d_in[2];
    const float* W1 = (const float*)d_in[3];
    const float* b1 = (const float*)d_in[4];
    const float* g1 = (const float*)d_in[5];
    const float* be1= (const float*)d_in[6];
    const float* W2 = (const float*)d_in[7];
    const float* b2 = (const float*)d_in[8];
    const float* g2 = (const float*)d_in[9];
    const float* be2= (const float*)d_in[10];
    const float* W3 = (const float*)d_in[11];
    const float* b3 = (const float*)d_in[12];
    const float* g3 = (const float*)d_in[13];
    const float* be3= (const float*)d_in[14];
    const float* W4 = (const float*)d_in[15];
    const float* b4 = (const float*)d_in[16];
    const float* g4 = (const float*)d_in[17];
    const float* be4= (const float*)d_in[18];
    float* out = (float*)d_out;

    // scatter: 4 edges per thread (agg buffers pre-zeroed by previous mlp run
    // or BSS init on the very first launch)
    scatter_kernel<<<(E_EDGES / 4 * 4 + 255) / 256, 256>>>(nodes, edges4, ew4);

    int smCount = 148;
    cudaDeviceGetAttribute(&smCount, cudaDevAttrMultiProcessorCount, 0);
    cudaFuncSetAttribute(mlp_kernel, cudaFuncAttributeMaxDynamicSharedMemorySize, SMEM_BYTES);
    mlp_kernel<<<smCount, TPB, SMEM_BYTES>>>(nodes,
                                             W1, b1, g1, be1,
                                             W2, b2, g2, be2,
                                             W3, b3, g3, be3,
                                             W4, b4, g4, be4,
                                             out);
}

// round 16
// speedup vs baseline: 1.6446x; 1.0122x over previous
#include <cuda_runtime.h>
#include <cuda_fp16.h>
#include <cstdint>

#define N_NODES 100000
#define E_EDGES 3200000
#define NTILES  6250        // 100000 / 16 exactly
#define LN_EPS  1e-5f
#define TPB     256
#define WPB     8

// ---------------- scratch ----------------------------------------------------
// starts zeroed (BSS); mlp_kernel re-zeroes consumed rows each run, so the
// zero invariant holds across graph replays without memset nodes.
__device__ __align__(16) float g_agg_in [N_NODES * 16];
__device__ __align__(16) float g_agg_out[N_NODES * 16];

// ---------------- edge scatter (4 edges / thread, fp32) ----------------------
__device__ __forceinline__ void red_add_v4(float* p, float a, float b, float c, float d) {
    asm volatile("red.global.add.v4.f32 [%0], {%1,%2,%3,%4};"
                 :: "l"(p), "f"(a), "f"(b), "f"(c), "f"(d) : "memory");
}

__device__ __forceinline__ void scat1(const float* __restrict__ nodes,
                                      int s, int d, float w, int c4) {
    float4 ns = *(const float4*)&nodes[s * 16 + c4];
    float4 nd = *(const float4*)&nodes[d * 16 + c4];
    red_add_v4(&g_agg_in [d * 16 + c4], ns.x * w, ns.y * w, ns.z * w, ns.w * w);
    red_add_v4(&g_agg_out[s * 16 + c4], nd.x * w, nd.y * w, nd.z * w, nd.w * w);
}

__global__ void __launch_bounds__(256)
scatter_kernel(const float* __restrict__ nodes,
               const int4*  __restrict__ edges4,    // edge pairs: (s,d,s,d)
               const float4* __restrict__ ew4) {
    // allow the dependent mlp kernel to begin launching immediately; it only
    // touches agg buffers after griddepcontrol.wait (= our full completion).
    asm volatile("griddepcontrol.launch_dependents;" ::: "memory");
    int tid = blockIdx.x * 256 + threadIdx.x;
    int q = tid >> 2;                      // edge-quad index
    if (q >= E_EDGES / 4) return;
    int c4 = (tid & 3) * 4;
    int4   e01 = edges4[2 * q];
    int4   e23 = edges4[2 * q + 1];
    float4 w   = ew4[q];
    scat1(nodes, e01.x, e01.y, w.x, c4);
    scat1(nodes, e01.z, e01.w, w.y, c4);
    scat1(nodes, e23.x, e23.y, w.z, c4);
    scat1(nodes, e23.z, e23.w, w.w, c4);
}

// ============ warp-MMA MLP (fp16 2-term split, fragment-major B) =============
#define OFF_L1 0
#define OFF_L2 3072
#define OFF_L3 11264
#define OFF_L4 19456
#define OFF_PB 20480
#define SMEM_U32 (OFF_PB + 1200)
#define SMEM_BYTES (SMEM_U32 * 4)

__device__ __forceinline__ void mma16816f(float d[4], const uint32_t a[4],
                                          uint32_t b0, uint32_t b1) {
    asm volatile("mma.sync.aligned.m16n8k16.row.col.f32.f16.f16.f32 "
                 "{%0,%1,%2,%3}, {%4,%5,%6,%7}, {%8,%9}, {%0,%1,%2,%3};"
                 : "+f"(d[0]), "+f"(d[1]), "+f"(d[2]), "+f"(d[3])
                 : "r"(a[0]), "r"(a[1]), "r"(a[2]), "r"(a[3]), "r"(b0), "r"(b1));
}
__device__ __forceinline__ void mma16816f_z(float d[4], const uint32_t a[4],
                                            uint32_t b0, uint32_t b1) {
    asm volatile("mma.sync.aligned.m16n8k16.row.col.f32.f16.f16.f32 "
                 "{%0,%1,%2,%3}, {%4,%5,%6,%7}, {%8,%9}, {%10,%10,%10,%10};"
                 : "=f"(d[0]), "=f"(d[1]), "=f"(d[2]), "=f"(d[3])
                 : "r"(a[0]), "r"(a[1]), "r"(a[2]), "r"(a[3]), "r"(b0), "r"(b1),
                   "f"(0.0f));
}

__device__ __forceinline__ void ldsm2(uint32_t& r0, uint32_t& r1, uint32_t addr) {
    asm volatile("ldmatrix.sync.aligned.m8n8.x2.shared.b16 {%0,%1}, [%2];"
                 : "=r"(r0), "=r"(r1) : "r"(addr));
}

__device__ __forceinline__ uint32_t smem_u32(const void* p) {
    uint32_t a;
    asm("{ .reg .u64 t; cvta.to.shared.u64 t, %1; cvt.u32.u64 %0, t; }" : "=r"(a) : "l"(p));
    return a;
}

// fp16 split: hi + residual
__device__ __forceinline__ uint32_t pack_hi(float a, float b, float& ra, float& rb) {
    __half2 h2 = __floats2half2_rn(a, b);
    ra = a - __half2float(__low2half(h2));
    rb = b - __half2float(__high2half(h2));
    return *reinterpret_cast<uint32_t*>(&h2);
}
__device__ __forceinline__ uint32_t pack_f16(float a, float b) {
    __half2 h2 = __floats2half2_rn(a, b);
    return *reinterpret_cast<uint32_t*>(&h2);
}

__device__ __forceinline__ float ptanh(float x) {
    float y;
    asm("tanh.approx.f32 %0, %1;" : "=f"(y) : "f"(x));
    return y;
}
__device__ __forceinline__ float ftanh(float x) {
    float t = fminf(fmaxf(2.0f * x, -60.0f), 60.0f);
    float e = __expf(t);
    return __fdividef(e - 1.0f, e + 1.0f);
}

// stage W[K][N] -> fragment-major blocks
__device__ void stage_w(const float* __restrict__ W, uint32_t* __restrict__ dst,
                        int K, int N, int KT, int tid, int tpb) {
    const int half = K >> 1;
    for (int idx = tid; idx < N * half; idx += tpb) {
        int n = idx / half, kk = idx - n * half;
        int k = 2 * kk;
        int kt = k >> 4, hf = (k >> 3) & 1, kc = (k & 7) >> 1;
        int nt = n >> 3, row = n & 7;
        dst[((nt * KT + kt) * 2 + hf) * 32 + row * 4 + kc] =
            pack_f16(W[k * N + n], W[(k + 1) * N + n]);
    }
}

// D[nt] = (Ahi + Alo) x W ; all ldsm addresses = fbase + immediate
template <int KT, int NTt>
__device__ __forceinline__ void layer_mma(const uint32_t Ahi[][4], const uint32_t Alo[][4],
                                          uint32_t fbase, float D[][4]) {
#pragma unroll
    for (int nt = 0; nt < NTt; nt++) {
        uint32_t b0, b1;
        ldsm2(b0, b1, fbase + (uint32_t)(nt * KT) * 256u);
        mma16816f_z(D[nt], Ahi[0], b0, b1);
        mma16816f(D[nt], Alo[0], b0, b1);
#pragma unroll
        for (int kt = 1; kt < KT; kt++) {
            ldsm2(b0, b1, fbase + (uint32_t)(nt * KT + kt) * 256u);
            mma16816f(D[nt], Ahi[kt], b0, b1);
            mma16816f(D[nt], Alo[kt], b0, b1);
        }
    }
}

// bias + LN(128) + tanh on D, emit next-layer A fragments (hi/lo fp16)
__device__ __forceinline__ void epi128(float D[][4], const float* __restrict__ Pb, int base,
                                       int tig, uint32_t Ahi[][4], uint32_t Alo[][4]) {
    const float* bias = Pb + base;
    const float* gain = Pb + base + 128;
    const float* beta = Pb + base + 256;
    float s0 = 0.f, q0 = 0.f, s1 = 0.f, q1 = 0.f;
#pragma unroll
    for (int nt = 0; nt < 16; nt++) {
        float2 bb = *(const float2*)&bias[nt * 8 + tig * 2];
        D[nt][0] += bb.x; D[nt][1] += bb.y;
        D[nt][2] += bb.x; D[nt][3] += bb.y;
        s0 += D[nt][0] + D[nt][1];
        q0 = fmaf(D[nt][0], D[nt][0], fmaf(D[nt][1], D[nt][1], q0));
        s1 += D[nt][2] + D[nt][3];
        q1 = fmaf(D[nt][2], D[nt][2], fmaf(D[nt][3], D[nt][3], q1));
    }
    s0 += __shfl_xor_sync(0xffffffffu, s0, 1); q0 += __shfl_xor_sync(0xffffffffu, q0, 1);
    s0 += __shfl_xor_sync(0xffffffffu, s0, 2); q0 += __shfl_xor_sync(0xffffffffu, q0, 2);
    s1 += __shfl_xor_sync(0xffffffffu, s1, 1); q1 += __shfl_xor_sync(0xffffffffu, q1, 1);
    s1 += __shfl_xor_sync(0xffffffffu, s1, 2); q1 += __shfl_xor_sync(0xffffffffu, q1, 2);
    float m0 = s0 * (1.0f / 128.0f);
    float v0 = fmaxf(q0 * (1.0f / 128.0f) - m0 * m0, 0.0f);
    float rs0 = rsqrtf(v0 + LN_EPS);
    float m1 = s1 * (1.0f / 128.0f);
    float v1 = fmaxf(q1 * (1.0f / 128.0f) - m1 * m1, 0.0f);
    float rs1 = rsqrtf(v1 + LN_EPS);
#pragma unroll
    for (int kt = 0; kt < 8; kt++) {
#pragma unroll
        for (int h = 0; h < 2; h++) {
            int nt = 2 * kt + h;
            float2 gg = *(const float2*)&gain[nt * 8 + tig * 2];
            float2 be = *(const float2*)&beta[nt * 8 + tig * 2];
            float y0 = ptanh(fmaf((D[nt][0] - m0) * rs0, gg.x, be.x));
            float y1 = ptanh(fmaf((D[nt][1] - m0) * rs0, gg.y, be.y));
            float y2 = ptanh(fmaf((D[nt][2] - m1) * rs1, gg.x, be.x));
            float y3 = ptanh(fmaf((D[nt][3] - m1) * rs1, gg.y, be.y));
            float ra, rb;
            Ahi[kt][0 + 2 * h] = pack_hi(y0, y1, ra, rb);
            Alo[kt][0 + 2 * h] = pack_f16(ra, rb);
            Ahi[kt][1 + 2 * h] = pack_hi(y2, y3, ra, rb);
            Alo[kt][1 + 2 * h] = pack_f16(ra, rb);
        }
    }
}

__global__ void __launch_bounds__(TPB, 1)
mlp_kernel(const float* __restrict__ nodes,
           const float* __restrict__ W1, const float* __restrict__ b1,
           const float* __restrict__ g1, const float* __restrict__ be1,
           const float* __restrict__ W2, const float* __restrict__ b2,
           const float* __restrict__ g2, const float* __restrict__ be2,
           const float* __restrict__ W3, const float* __restrict__ b3,
           const float* __restrict__ g3, const float* __restrict__ be3,
           const float* __restrict__ W4, const float* __restrict__ b4,
           const float* __restrict__ g4, const float* __restrict__ be4,
           float* __restrict__ out) {
    extern __shared__ uint32_t smw[];
    float* Pb = (float*)(smw + OFF_PB);
    const int tid = threadIdx.x;

    // ---- stage weights (fp16, fragment-major) — independent of scatter ----
    stage_w(W1, smw + OFF_L1,  48, 128, 3, tid, TPB);
    stage_w(W2, smw + OFF_L2, 128, 128, 8, tid, TPB);
    stage_w(W3, smw + OFF_L3, 128, 128, 8, tid, TPB);
    stage_w(W4, smw + OFF_L4, 128,  16, 8, tid, TPB);
    for (int i = tid; i < 128; i += TPB) {
        Pb[0 + i]   = b1[i]; Pb[128 + i] = g1[i]; Pb[256 + i]  = be1[i];
        Pb[384 + i] = b2[i]; Pb[512 + i] = g2[i]; Pb[640 + i]  = be2[i];
        Pb[768 + i] = b3[i]; Pb[896 + i] = g3[i]; Pb[1024 + i] = be3[i];
    }
    for (int i = tid; i < 16; i += TPB) {
        Pb[1152 + i] = b4[i]; Pb[1168 + i] = g4[i]; Pb[1184 + i] = be4[i];
    }
    __syncthreads();

    // ---- wait for scatter_kernel completion (PDL) before reading agg ----
    asm volatile("griddepcontrol.wait;" ::: "memory");

    const int warp = tid >> 5, lane = tid & 31;
    const int grp = lane >> 2, tig = lane & 3;
    const int lane16 = lane & 15;
    const uint32_t fconst = (uint32_t)(lane16 >> 3) * 128u + (uint32_t)(lane16 & 7) * 16u;
    const uint32_t smbase = smem_u32(smw);
    const uint32_t fb1 = smbase + OFF_L1 * 4u + fconst;
    const uint32_t fb2 = smbase + OFF_L2 * 4u + fconst;
    const uint32_t fb3 = smbase + OFF_L3 * 4u + fconst;
    const uint32_t fb4 = smbase + OFF_L4 * 4u + fconst;

    uint32_t Ahi[8][4], Alo[8][4];
    float D[16][4];

    for (int t = blockIdx.x * WPB + warp; t < NTILES; t += gridDim.x * WPB) {
        const int r0 = t * 16 + grp, r1 = r0 + 8;

        // ---- layer-1 A fragments from [agg_in | agg_out | nodes] ----
#pragma unroll
        for (int kt = 0; kt < 3; kt++) {
            const float* S = (kt == 0) ? g_agg_in : (kt == 1) ? g_agg_out : nodes;
            float2 x00 = *(const float2*)&S[r0 * 16 + tig * 2];
            float2 x01 = *(const float2*)&S[r0 * 16 + 8 + tig * 2];
            float2 x10 = *(const float2*)&S[r1 * 16 + tig * 2];
            float2 x11 = *(const float2*)&S[r1 * 16 + 8 + tig * 2];
            float ra, rb;
            Ahi[kt][0] = pack_hi(x00.x, x00.y, ra, rb); Alo[kt][0] = pack_f16(ra, rb);
            Ahi[kt][1] = pack_hi(x10.x, x10.y, ra, rb); Alo[kt][1] = pack_f16(ra, rb);
            Ahi[kt][2] = pack_hi(x01.x, x01.y, ra, rb); Alo[kt][2] = pack_f16(ra, rb);
            Ahi[kt][3] = pack_hi(x11.x, x11.y, ra, rb); Alo[kt][3] = pack_f16(ra, rb);
        }

        layer_mma<3, 16>(Ahi, Alo, fb1, D);
        epi128(D, Pb, 0, tig, Ahi, Alo);
        layer_mma<8, 16>(Ahi, Alo, fb2, D);
        epi128(D, Pb, 384, tig, Ahi, Alo);
        layer_mma<8, 16>(Ahi, Alo, fb3, D);
        epi128(D, Pb, 768, tig, Ahi, Alo);
        layer_mma<8, 2>(Ahi, Alo, fb4, D);

        // ---- layer-4 epilogue: LN(16)+tanh (accurate), write out ----
        {
            float2 bb0 = *(const float2*)&Pb[1152 + tig * 2];
            float2 bb1 = *(const float2*)&Pb[1152 + 8 + tig * 2];
            float v00 = D[0][0] + bb0.x, v01 = D[0][1] + bb0.y;
            float v02 = D[1][0] + bb1.x, v03 = D[1][1] + bb1.y;
            float v10 = D[0][2] + bb0.x, v11 = D[0][3] + bb0.y;
            float v12 = D[1][2] + bb1.x, v13 = D[1][3] + bb1.y;
            float s0 = (v00 + v01) + (v02 + v03);
            float q0 = fmaf(v00, v00, fmaf(v01, v01, fmaf(v02, v02, v03 * v03)));
            float s1 = (v10 + v11) + (v12 + v13);
            float q1 = fmaf(v10, v10, fmaf(v11, v11, fmaf(v12, v12, v13 * v13)));
            s0 += __shfl_xor_sync(0xffffffffu, s0, 1); q0 += __shfl_xor_sync(0xffffffffu, q0, 1);
            s0 += __shfl_xor_sync(0xffffffffu, s0, 2); q0 += __shfl_xor_sync(0xffffffffu, q0, 2);
            s1 += __shfl_xor_sync(0xffffffffu, s1, 1); q1 += __shfl_xor_sync(0xffffffffu, q1, 1);
            s1 += __shfl_xor_sync(0xffffffffu, s1, 2); q1 += __shfl_xor_sync(0xffffffffu, q1, 2);
            float m0 = s0 * (1.0f / 16.0f);
            float w0 = fmaxf(q0 * (1.0f / 16.0f) - m0 * m0, 0.0f);
            float rs0 = rsqrtf(w0 + LN_EPS);
            float m1 = s1 * (1.0f / 16.0f);
            float w1 = fmaxf(q1 * (1.0f / 16.0f) - m1 * m1, 0.0f);
            float rs1 = rsqrtf(w1 + LN_EPS);
            float2 gg0 = *(const float2*)&Pb[1168 + tig * 2];
            float2 gg1 = *(const float2*)&Pb[1168 + 8 + tig * 2];
            float2 be0 = *(const float2*)&Pb[1184 + tig * 2];
            float2 be1v = *(const float2*)&Pb[1184 + 8 + tig * 2];
            float2 o;
            o.x = ftanh(fmaf((v00 - m0) * rs0, gg0.x, be0.x));
            o.y = ftanh(fmaf((v01 - m0) * rs0, gg0.y, be0.y));
            *(float2*)&out[r0 * 16 + tig * 2] = o;
            o.x = ftanh(fmaf((v02 - m0) * rs0, gg1.x, be1v.x));
            o.y = ftanh(fmaf((v03 - m0) * rs0, gg1.y, be1v.y));
            *(float2*)&out[r0 * 16 + 8 + tig * 2] = o;
            o.x = ftanh(fmaf((v10 - m1) * rs1, gg0.x, be0.x));
            o.y = ftanh(fmaf((v11 - m1) * rs1, gg0.y, be0.y));
            *(float2*)&out[r1 * 16 + tig * 2] = o;
            o.x = ftanh(fmaf((v12 - m1) * rs1, gg1.x, be1v.x));
            o.y = ftanh(fmaf((v13 - m1) * rs1, gg1.y, be1v.y));
            *(float2*)&out[r1 * 16 + 8 + tig * 2] = o;
        }

        // ---- re-zero this tile's agg rows for the next graph replay ----
        {
            const float4 z = make_float4(0.f, 0.f, 0.f, 0.f);
            *(float4*)&g_agg_in [r0 * 16 + tig * 4] = z;
            *(float4*)&g_agg_in [r1 * 16 + tig * 4] = z;
            *(float4*)&g_agg_out[r0 * 16 + tig * 4] = z;
            *(float4*)&g_agg_out[r1 * 16 + tig * 4] = z;
        }
    }
}

// ---------------- launch -----------------------------------------------------
extern "C" void kernel_launch(void* const* d_in, const int* in_sizes, int n_in,
                              void* d_out, int out_size) {
    const float* nodes  = (const float*)d_in[0];
    const int4*  edges4 = (const int4*) d_in[1];
    const float4* ew4   = (const float4*)d_in[2];
    const float* W1 = (const float*)d_in[3];
    const float* b1 = (const float*)d_in[4];
    const float* g1 = (const float*)d_in[5];
    const float* be1= (const float*)d_in[6];
    const float* W2 = (const float*)d_in[7];
    const float* b2 = (const float*)d_in[8];
    const float* g2 = (const float*)d_in[9];
    const float* be2= (const float*)d_in[10];
    const float* W3 = (const float*)d_in[11];
    const float* b3 = (const float*)d_in[12];
    const float* g3 = (const float*)d_in[13];
    const float* be3= (const float*)d_in[14];
    const float* W4 = (const float*)d_in[15];
    const float* b4 = (const float*)d_in[16];
    const float* g4 = (const float*)d_in[17];
    const float* be4= (const float*)d_in[18];
    float* out = (float*)d_out;

    // scatter: 4 edges per thread
    scatter_kernel<<<(E_EDGES / 4 * 4 + 255) / 256, 256>>>(nodes, edges4, ew4);

    int smCount = 148;
    cudaDeviceGetAttribute(&smCount, cudaDevAttrMultiProcessorCount, 0);
    cudaFuncSetAttribute(mlp_kernel, cudaFuncAttributeMaxDynamicSharedMemorySize, SMEM_BYTES);

    // PDL launch: mlp may begin (and stage weights) while scatter drains;
    // griddepcontrol.wait inside mlp orders agg reads after scatter completion.
    cudaLaunchConfig_t cfg = {};
    cfg.gridDim = dim3((unsigned)smCount, 1, 1);
    cfg.blockDim = dim3(TPB, 1, 1);
    cfg.dynamicSmemBytes = SMEM_BYTES;
    cudaLaunchAttribute attrs[1];
    attrs[0].id = cudaLaunchAttributeProgrammaticStreamSerialization;
    attrs[0].val.programmaticStreamSerializationAllowed = 1;
    cfg.attrs = attrs;
    cfg.numAttrs = 1;
    cudaLaunchKernelEx(&cfg, mlp_kernel, nodes,
                       W1, b1, g1, be1,
                       W2, b2, g2, be2,
                       W3, b3, g3, be3,
                       W4, b4, g4, be4,
                       out);
}